// round 4
// baseline (speedup 1.0000x reference)
#include <cuda_runtime.h>
#include <cuda_bf16.h>

// Problem constants (from reference): B=16, V=4096, E=768
#define BB 16
#define VV 4096
#define EE 768

// out[b,v,e] = seq[b,v,0]*flux_w[v,e] + flux_b[v,e]
//            + seq[b,v,2]*time_w[v,e] + time_b[v,e]
//            + (e even ? sin : cos)( seq[b,v,1] * exp(-2*(e/2)*ln(10000)/E) )
//
// One block per v (4096 blocks), 192 threads, each thread owns 4 consecutive e.
// Weights are loaded ONCE per (v,e) into registers; the b-loop reuses them,
// keeping weight DRAM traffic at the compulsory 50 MB. Output writes (201 MB)
// dominate -> kernel is HBM-write-bound.
__global__ __launch_bounds__(192) void bert_embed_kernel(
    const float* __restrict__ seq,   // [B, V, 3]
    const float* __restrict__ fw,    // [V, E]
    const float* __restrict__ fb,    // [V, E]
    const float* __restrict__ tw,    // [V, E]
    const float* __restrict__ tb,    // [V, E]
    float* __restrict__ out)         // [B, V, E]
{
    const int v = blockIdx.x;
    const int e = threadIdx.x * 4;           // even-aligned
    const size_t base = (size_t)v * EE + e;

    // Compulsory weight reads, kept in registers across the batch loop.
    const float4 wf = *reinterpret_cast<const float4*>(fw + base);
    const float4 bf = *reinterpret_cast<const float4*>(fb + base);
    const float4 wt = *reinterpret_cast<const float4*>(tw + base);
    const float4 bt = *reinterpret_cast<const float4*>(tb + base);

    // div_term for the two sin/cos pairs this thread owns.
    // div_term[i] = exp(2i * (-ln(10000)/E)); here 2i = e and e+2.
    const float c = -9.210340371976184f / (float)EE;   // -ln(10000)/E
    const float d0 = __expf((float)e * c);
    const float d1 = __expf((float)(e + 2) * c);

    #pragma unroll
    for (int b = 0; b < BB; b++) {
        const float* s = seq + ((size_t)b * VV + v) * 3;
        const float s0 = __ldg(s + 0);   // flux scalar (broadcast across block)
        const float s1 = __ldg(s + 1);   // passend
        const float s2 = __ldg(s + 2);   // time

        float sin0, cos0, sin1, cos1;
        __sincosf(s1 * d0, &sin0, &cos0);
        __sincosf(s1 * d1, &sin1, &cos1);

        float4 o;
        o.x = fmaf(s0, wf.x, bf.x) + fmaf(s2, wt.x, bt.x) + sin0;
        o.y = fmaf(s0, wf.y, bf.y) + fmaf(s2, wt.y, bt.y) + cos0;
        o.z = fmaf(s0, wf.z, bf.z) + fmaf(s2, wt.z, bt.z) + sin1;
        o.w = fmaf(s0, wf.w, bf.w) + fmaf(s2, wt.w, bt.w) + cos1;

        *reinterpret_cast<float4*>(out + (size_t)b * (VV * EE) + base) = o;
    }
}

extern "C" void kernel_launch(void* const* d_in, const int* in_sizes, int n_in,
                              void* d_out, int out_size)
{
    const float* seq = (const float*)d_in[0];  // sequence [B,V,3]
    const float* fw  = (const float*)d_in[1];  // flux_w   [V,E]
    const float* fb  = (const float*)d_in[2];  // flux_b   [V,E]
    const float* tw  = (const float*)d_in[3];  // time_w   [V,E]
    const float* tb  = (const float*)d_in[4];  // time_b   [V,E]
    float* out = (float*)d_out;                // [B,V,E]

    dim3 grid(VV);
    dim3 block(EE / 4);  // 192 threads
    bert_embed_kernel<<<grid, block>>>(seq, fw, fb, tw, tb, out);
}